// round 15
// baseline (speedup 1.0000x reference)
#include <cuda_runtime.h>
#include <math.h>

#define T_  4
#define C_  512
#define H_  192
#define W_  192
#define HW_ (H_ * W_)
#define CHW_ ((size_t)C_ * HW_)
#define W4_ (W_ / 4)

struct TCoef { float ax, bx, cx, ay, by, cy; };
struct TInt  { int k4, ky, s; float fx, fy; };

__device__ float  g_part[C_ * 4];
__device__ TCoef  g_tc[T_];
__device__ TInt   g_ti[T_];
__device__ int    g_fast;
__device__ int    g_ky_min, g_ky_max, g_k4_min, g_k4_max;
__device__ float4 g_zero4;     // statically zero; never written — OOB load target

// ---------------------------------------------------------------------------
// Kernel 1: GAP, 4 partial blocks per channel (proven ~15us @ 61-66% DRAM)
// ---------------------------------------------------------------------------
__global__ void gap_kernel(const float* __restrict__ F) {
    int c = blockIdx.x >> 2;
    int q = blockIdx.x & 3;
    const int n4q = HW_ / 16;
    const float4* p = reinterpret_cast<const float4*>(F + (size_t)c * HW_) + q * n4q;
    float s = 0.f;
    #pragma unroll
    for (int i = 0; i < 9; ++i) {
        float4 v = p[i * 256 + threadIdx.x];
        s += (v.x + v.y) + (v.z + v.w);
    }
    #pragma unroll
    for (int o = 16; o > 0; o >>= 1) s += __shfl_xor_sync(0xffffffffu, s, o);
    __shared__ float sh[8];
    if ((threadIdx.x & 31) == 0) sh[threadIdx.x >> 5] = s;
    __syncthreads();
    if (threadIdx.x == 0) {
        float t = 0.f;
        #pragma unroll
        for (int i = 0; i < 8; ++i) t += sh[i];
        g_part[c * 4 + q] = t;
    }
}

// ---------------------------------------------------------------------------
// Kernel 2: theta (+ span mins/maxes for the interior test)
// ---------------------------------------------------------------------------
__global__ void theta_kernel(const float* __restrict__ w1,
                             const float* __restrict__ b1,
                             const float* __restrict__ a,
                             float* __restrict__ out_tail) {
    int warp = threadIdx.x >> 5;
    int lane = threadIdx.x & 31;

    float s = 0.f;
    for (int k = lane; k < C_; k += 32) {
        float4 pp = *reinterpret_cast<const float4*>(&g_part[4 * k]);
        s += ((pp.x + pp.y) + (pp.z + pp.w)) * w1[warp * C_ + k];
    }
    #pragma unroll
    for (int o = 16; o > 0; o >>= 1) s += __shfl_xor_sync(0xffffffffu, s, o);

    __shared__ float Bs[2 * T_];
    if (lane == 0) Bs[warp] = tanhf(s * (1.0f / (float)HW_) + b1[warp]);
    __syncthreads();

    float a00 = a[0], a01 = a[1], a10 = a[2], a11 = a[3];

    if (threadIdx.x == 0)
        g_fast = (a00 == 1.0f && a01 == 0.0f && a10 == 0.0f && a11 == 1.0f) ? 1 : 0;

    if (threadIdx.x < T_) {
        int t = threadIdx.x;
        float bx = Bs[2 * t + 0];
        float by = Bs[2 * t + 1];
        TCoef tc;
        tc.ax = a00;
        tc.bx = a01 * ((float)W_ / (float)H_);
        tc.cx = 0.5f * (a00 - a00 * (float)W_ + a01 * ((float)W_ / (float)H_)
                        - a01 * (float)W_ + bx * (float)W_ + (float)W_ - 1.0f);
        tc.ay = a10 * ((float)H_ / (float)W_);
        tc.by = a11;
        tc.cy = 0.5f * (a10 * ((float)H_ / (float)W_) - a10 * (float)H_ + a11
                        - a11 * (float)H_ + by * (float)H_ + (float)H_ - 1.0f);
        g_tc[t] = tc;

        TInt ti;
        float kxf = floorf(tc.cx), kyf = floorf(tc.cy);
        int kx = (int)kxf;
        ti.ky = (int)kyf;
        ti.fx = tc.cx - kxf;
        ti.fy = tc.cy - kyf;
        ti.s  = kx & 3;
        ti.k4 = kx >> 2;          // floor(kx/4), exact for negatives
        g_ti[t] = ti;
    }
    __syncthreads();

    if (threadIdx.x == 0) {
        int kymin = g_ti[0].ky, kymax = g_ti[0].ky;
        int k4min = g_ti[0].k4, k4max = g_ti[0].k4;
        for (int t = 1; t < T_; ++t) {
            kymin = min(kymin, g_ti[t].ky); kymax = max(kymax, g_ti[t].ky);
            k4min = min(k4min, g_ti[t].k4); k4max = max(k4max, g_ti[t].k4);
        }
        g_ky_min = kymin; g_ky_max = kymax;
        g_k4_min = k4min; g_k4_max = k4max;
    }

    if (threadIdx.x < T_ * 4) out_tail[threadIdx.x] = a[threadIdx.x & 3];
    if (threadIdx.x < 2 * T_) out_tail[T_ * 4 + threadIdx.x] = Bs[threadIdx.x];
}

// ---------------------------------------------------------------------------
// Kernel 3: bilinear warp. Interior threads (~94%, whole warps in the bulk)
// skip ALL bounds logic: direct loads, no selects. Border threads use the
// R14 zero-redirect path. Fallback path for general affine unchanged.
// ---------------------------------------------------------------------------
__global__ void __launch_bounds__(384) sample_kernel(const float* __restrict__ F,
                                                     float* __restrict__ out) {
    int w4 = threadIdx.x;                    // 0..47
    int h  = blockIdx.x * 8 + threadIdx.y;   // 0..191
    int c  = blockIdx.y;                     // 0..511
    int w0 = w4 * 4;

    const float* Fc = F + (size_t)c * HW_;
    float* outp = out + (size_t)c * HW_ + (size_t)h * W_ + w0;

    if (g_fast) {
        bool all_in = (h + g_ky_min >= 0) && (h + g_ky_max + 1 < H_)
                   && (w4 + g_k4_min >= 0) && (w4 + g_k4_max + 2 <= W4_);

        if (all_in) {
            // ---- interior: zero bounds logic ----
            #pragma unroll
            for (int t = 0; t < T_; ++t) {
                TInt ti = g_ti[t];
                const float4* r0 = reinterpret_cast<const float4*>(Fc)
                                   + (h + ti.ky) * W4_ + (w4 + ti.k4);
                const float4* r1 = r0 + W4_;

                float4 A0 = __ldg(r0);
                float4 A1 = __ldg(r0 + 1);
                float4 B0 = __ldg(r1);
                float4 B1 = __ldg(r1 + 1);

                float fy = ti.fy;
                float m0 = A0.x + fy * (B0.x - A0.x);
                float m1 = A0.y + fy * (B0.y - A0.y);
                float m2 = A0.z + fy * (B0.z - A0.z);
                float m3 = A0.w + fy * (B0.w - A0.w);
                float m4 = A1.x + fy * (B1.x - A1.x);
                float m5 = A1.y + fy * (B1.y - A1.y);
                float m6 = A1.z + fy * (B1.z - A1.z);
                float m7 = A1.w + fy * (B1.w - A1.w);

                float fx = ti.fx;
                float4 o;
                #define MIX_(e0, e1) ((e0) + fx * ((e1) - (e0)))
                switch (ti.s) {
                    case 0: o.x=MIX_(m0,m1); o.y=MIX_(m1,m2); o.z=MIX_(m2,m3); o.w=MIX_(m3,m4); break;
                    case 1: o.x=MIX_(m1,m2); o.y=MIX_(m2,m3); o.z=MIX_(m3,m4); o.w=MIX_(m4,m5); break;
                    case 2: o.x=MIX_(m2,m3); o.y=MIX_(m3,m4); o.z=MIX_(m4,m5); o.w=MIX_(m5,m6); break;
                    default:o.x=MIX_(m3,m4); o.y=MIX_(m4,m5); o.z=MIX_(m5,m6); o.w=MIX_(m6,m7); break;
                }
                #undef MIX_
                __stcs(reinterpret_cast<float4*>(outp + (size_t)t * CHW_), o);
            }
        } else {
            // ---- border: zero-redirect loads (R14 path) ----
            const float4* zp = &g_zero4;
            #pragma unroll
            for (int t = 0; t < T_; ++t) {
                TInt ti = g_ti[t];
                int y0 = h + ti.ky;
                int base4 = w4 + ti.k4;
                bool vy0 = (unsigned)y0       < (unsigned)H_;
                bool vy1 = (unsigned)(y0 + 1) < (unsigned)H_;
                bool k0  = (unsigned)base4       < (unsigned)W4_;
                bool k1  = (unsigned)(base4 + 1) < (unsigned)W4_;

                const float4* r0 = reinterpret_cast<const float4*>(Fc) + y0 * W4_;
                const float4* r1 = r0 + W4_;

                const float4* q00 = (vy0 && k0) ? r0 + base4     : zp;
                const float4* q01 = (vy0 && k1) ? r0 + base4 + 1 : zp;
                const float4* q10 = (vy1 && k0) ? r1 + base4     : zp;
                const float4* q11 = (vy1 && k1) ? r1 + base4 + 1 : zp;

                float4 A0 = __ldg(q00);
                float4 A1 = __ldg(q01);
                float4 B0 = __ldg(q10);
                float4 B1 = __ldg(q11);

                float fy = ti.fy;
                float m0 = A0.x + fy * (B0.x - A0.x);
                float m1 = A0.y + fy * (B0.y - A0.y);
                float m2 = A0.z + fy * (B0.z - A0.z);
                float m3 = A0.w + fy * (B0.w - A0.w);
                float m4 = A1.x + fy * (B1.x - A1.x);
                float m5 = A1.y + fy * (B1.y - A1.y);
                float m6 = A1.z + fy * (B1.z - A1.z);
                float m7 = A1.w + fy * (B1.w - A1.w);

                float fx = ti.fx;
                float4 o;
                #define MIX_(e0, e1) ((e0) + fx * ((e1) - (e0)))
                switch (ti.s) {
                    case 0: o.x=MIX_(m0,m1); o.y=MIX_(m1,m2); o.z=MIX_(m2,m3); o.w=MIX_(m3,m4); break;
                    case 1: o.x=MIX_(m1,m2); o.y=MIX_(m2,m3); o.z=MIX_(m3,m4); o.w=MIX_(m4,m5); break;
                    case 2: o.x=MIX_(m2,m3); o.y=MIX_(m3,m4); o.z=MIX_(m4,m5); o.w=MIX_(m5,m6); break;
                    default:o.x=MIX_(m3,m4); o.y=MIX_(m4,m5); o.z=MIX_(m5,m6); o.w=MIX_(m6,m7); break;
                }
                #undef MIX_
                __stcs(reinterpret_cast<float4*>(outp + (size_t)t * CHW_), o);
            }
        }
    } else {
        // General affine fallback (scalar gathers)
        #pragma unroll
        for (int t = 0; t < T_; ++t) {
            TCoef tc = g_tc[t];
            float bases_x = tc.bx * (float)h + tc.cx;
            float bases_y = tc.by * (float)h + tc.cy;
            float4 o;
            float* op = reinterpret_cast<float*>(&o);
            #pragma unroll
            for (int j = 0; j < 4; ++j) {
                float wf = (float)(w0 + j);
                float ix = tc.ax * wf + bases_x;
                float iy = tc.ay * wf + bases_y;
                float ix0f = floorf(ix), iy0f = floorf(iy);
                float fx = ix - ix0f,   fy = iy - iy0f;
                int x0 = (int)ix0f, y0 = (int)iy0f;
                int x1 = x0 + 1,    y1 = y0 + 1;
                bool vx0 = (unsigned)x0 < (unsigned)W_;
                bool vx1 = (unsigned)x1 < (unsigned)W_;
                bool vy0 = (unsigned)y0 < (unsigned)H_;
                bool vy1 = (unsigned)y1 < (unsigned)H_;
                const float* r0 = Fc + (size_t)(vy0 ? y0 : 0) * W_;
                const float* r1 = Fc + (size_t)(vy1 ? y1 : 0) * W_;
                float v00 = (vy0 && vx0) ? __ldg(r0 + x0) : 0.f;
                float v01 = (vy0 && vx1) ? __ldg(r0 + x1) : 0.f;
                float v10 = (vy1 && vx0) ? __ldg(r1 + x0) : 0.f;
                float v11 = (vy1 && vx1) ? __ldg(r1 + x1) : 0.f;
                float wx0 = 1.f - fx, wx1 = fx;
                float wy0 = 1.f - fy, wy1 = fy;
                op[j] = wy0 * (wx0 * v00 + wx1 * v01) + wy1 * (wx0 * v10 + wx1 * v11);
            }
            __stcs(reinterpret_cast<float4*>(outp + (size_t)t * CHW_), o);
        }
    }
}

// ---------------------------------------------------------------------------
extern "C" void kernel_launch(void* const* d_in, const int* in_sizes, int n_in,
                              void* d_out, int out_size) {
    const float* F  = (const float*)d_in[0];
    const float* w1 = (const float*)d_in[1];
    const float* b1 = (const float*)d_in[2];
    const float* a  = (const float*)d_in[3];
    float* out = (float*)d_out;

    float* out_tail = out + (size_t)T_ * CHW_;

    gap_kernel<<<C_ * 4, 256>>>(F);
    theta_kernel<<<1, 256>>>(w1, b1, a, out_tail);

    dim3 blk(48, 8);              // 384 threads: w4 x 8 rows
    dim3 grd(H_ / 8, C_);         // 24 x 512 blocks
    sample_kernel<<<grd, blk>>>(F, out);
}

// round 16
// speedup vs baseline: 1.3342x; 1.3342x over previous
#include <cuda_runtime.h>
#include <math.h>

#define T_  4
#define C_  512
#define H_  192
#define W_  192
#define HW_ (H_ * W_)
#define CHW_ ((size_t)C_ * HW_)
#define W4_ (W_ / 4)

struct TCoef { float ax, bx, cx, ay, by, cy; };
struct TInt  { int k4, ky, s; float fx, fy; };

__device__ float  g_part[C_ * 4];
__device__ TCoef  g_tc[T_];
__device__ TInt   g_ti[T_];
__device__ int    g_fast;
__device__ float4 g_zero4;     // statically zero; never written — OOB load target

// ---------------------------------------------------------------------------
// Kernel 1: GAP, 4 partial blocks per channel (proven ~15us @ 61-66% DRAM)
// ---------------------------------------------------------------------------
__global__ void gap_kernel(const float* __restrict__ F) {
    int c = blockIdx.x >> 2;
    int q = blockIdx.x & 3;
    const int n4q = HW_ / 16;
    const float4* p = reinterpret_cast<const float4*>(F + (size_t)c * HW_) + q * n4q;
    float s = 0.f;
    #pragma unroll
    for (int i = 0; i < 9; ++i) {
        float4 v = p[i * 256 + threadIdx.x];
        s += (v.x + v.y) + (v.z + v.w);
    }
    #pragma unroll
    for (int o = 16; o > 0; o >>= 1) s += __shfl_xor_sync(0xffffffffu, s, o);
    __shared__ float sh[8];
    if ((threadIdx.x & 31) == 0) sh[threadIdx.x >> 5] = s;
    __syncthreads();
    if (threadIdx.x == 0) {
        float t = 0.f;
        #pragma unroll
        for (int i = 0; i < 8; ++i) t += sh[i];
        g_part[c * 4 + q] = t;
    }
}

// ---------------------------------------------------------------------------
// Kernel 2: theta
// ---------------------------------------------------------------------------
__global__ void theta_kernel(const float* __restrict__ w1,
                             const float* __restrict__ b1,
                             const float* __restrict__ a,
                             float* __restrict__ out_tail) {
    int warp = threadIdx.x >> 5;
    int lane = threadIdx.x & 31;

    float s = 0.f;
    for (int k = lane; k < C_; k += 32) {
        float4 pp = *reinterpret_cast<const float4*>(&g_part[4 * k]);
        s += ((pp.x + pp.y) + (pp.z + pp.w)) * w1[warp * C_ + k];
    }
    #pragma unroll
    for (int o = 16; o > 0; o >>= 1) s += __shfl_xor_sync(0xffffffffu, s, o);

    __shared__ float Bs[2 * T_];
    if (lane == 0) Bs[warp] = tanhf(s * (1.0f / (float)HW_) + b1[warp]);
    __syncthreads();

    float a00 = a[0], a01 = a[1], a10 = a[2], a11 = a[3];

    if (threadIdx.x == 0)
        g_fast = (a00 == 1.0f && a01 == 0.0f && a10 == 0.0f && a11 == 1.0f) ? 1 : 0;

    if (threadIdx.x < T_) {
        int t = threadIdx.x;
        float bx = Bs[2 * t + 0];
        float by = Bs[2 * t + 1];
        TCoef tc;
        tc.ax = a00;
        tc.bx = a01 * ((float)W_ / (float)H_);
        tc.cx = 0.5f * (a00 - a00 * (float)W_ + a01 * ((float)W_ / (float)H_)
                        - a01 * (float)W_ + bx * (float)W_ + (float)W_ - 1.0f);
        tc.ay = a10 * ((float)H_ / (float)W_);
        tc.by = a11;
        tc.cy = 0.5f * (a10 * ((float)H_ / (float)W_) - a10 * (float)H_ + a11
                        - a11 * (float)H_ + by * (float)H_ + (float)H_ - 1.0f);
        g_tc[t] = tc;

        TInt ti;
        float kxf = floorf(tc.cx), kyf = floorf(tc.cy);
        int kx = (int)kxf;
        ti.ky = (int)kyf;
        ti.fx = tc.cx - kxf;
        ti.fy = tc.cy - kyf;
        ti.s  = kx & 3;
        ti.k4 = kx >> 2;          // floor(kx/4), exact for negatives
        g_ti[t] = ti;
    }

    if (threadIdx.x < T_ * 4) out_tail[threadIdx.x] = a[threadIdx.x & 3];
    if (threadIdx.x < 2 * T_) out_tail[T_ * 4 + threadIdx.x] = Bs[threadIdx.x];
}

// ---------------------------------------------------------------------------
// Kernel 3: bilinear warp (R14, proven 98.75us). Zero-redirect pointer trick
// for OOB; flat predication, no branches. Only change vs R14: all four TInt
// hoisted before the unrolled loop so address setup front-batches the loads.
// ---------------------------------------------------------------------------
__global__ void __launch_bounds__(384) sample_kernel(const float* __restrict__ F,
                                                     float* __restrict__ out) {
    int w4 = threadIdx.x;                    // 0..47
    int h  = blockIdx.x * 8 + threadIdx.y;   // 0..191
    int c  = blockIdx.y;                     // 0..511
    int w0 = w4 * 4;

    const float* Fc = F + (size_t)c * HW_;
    float* outp = out + (size_t)c * HW_ + (size_t)h * W_ + w0;
    const float4* zp = &g_zero4;

    if (g_fast) {
        TInt ti0 = g_ti[0], ti1 = g_ti[1], ti2 = g_ti[2], ti3 = g_ti[3];
        TInt tis[T_] = { ti0, ti1, ti2, ti3 };
        #pragma unroll
        for (int t = 0; t < T_; ++t) {
            TInt ti = tis[t];
            int y0 = h + ti.ky;
            int base4 = w4 + ti.k4;
            bool vy0 = (unsigned)y0       < (unsigned)H_;
            bool vy1 = (unsigned)(y0 + 1) < (unsigned)H_;
            bool k0  = (unsigned)base4       < (unsigned)W4_;
            bool k1  = (unsigned)(base4 + 1) < (unsigned)W4_;

            const float4* r0 = reinterpret_cast<const float4*>(Fc) + y0 * W4_;
            const float4* r1 = r0 + W4_;

            const float4* q00 = (vy0 && k0) ? r0 + base4     : zp;
            const float4* q01 = (vy0 && k1) ? r0 + base4 + 1 : zp;
            const float4* q10 = (vy1 && k0) ? r1 + base4     : zp;
            const float4* q11 = (vy1 && k1) ? r1 + base4 + 1 : zp;

            float4 A0 = __ldg(q00);
            float4 A1 = __ldg(q01);
            float4 B0 = __ldg(q10);
            float4 B1 = __ldg(q11);

            float fy = ti.fy;
            float m0 = A0.x + fy * (B0.x - A0.x);
            float m1 = A0.y + fy * (B0.y - A0.y);
            float m2 = A0.z + fy * (B0.z - A0.z);
            float m3 = A0.w + fy * (B0.w - A0.w);
            float m4 = A1.x + fy * (B1.x - A1.x);
            float m5 = A1.y + fy * (B1.y - A1.y);
            float m6 = A1.z + fy * (B1.z - A1.z);
            float m7 = A1.w + fy * (B1.w - A1.w);

            float fx = ti.fx;
            float4 o;
            #define MIX_(e0, e1) ((e0) + fx * ((e1) - (e0)))
            switch (ti.s) {   // uniform branch: all warps take the same case
                case 0: o.x=MIX_(m0,m1); o.y=MIX_(m1,m2); o.z=MIX_(m2,m3); o.w=MIX_(m3,m4); break;
                case 1: o.x=MIX_(m1,m2); o.y=MIX_(m2,m3); o.z=MIX_(m3,m4); o.w=MIX_(m4,m5); break;
                case 2: o.x=MIX_(m2,m3); o.y=MIX_(m3,m4); o.z=MIX_(m4,m5); o.w=MIX_(m5,m6); break;
                default:o.x=MIX_(m3,m4); o.y=MIX_(m4,m5); o.z=MIX_(m5,m6); o.w=MIX_(m6,m7); break;
            }
            #undef MIX_
            __stcs(reinterpret_cast<float4*>(outp + (size_t)t * CHW_), o);
        }
    } else {
        // General affine fallback (scalar gathers)
        #pragma unroll
        for (int t = 0; t < T_; ++t) {
            TCoef tc = g_tc[t];
            float bases_x = tc.bx * (float)h + tc.cx;
            float bases_y = tc.by * (float)h + tc.cy;
            float4 o;
            float* op = reinterpret_cast<float*>(&o);
            #pragma unroll
            for (int j = 0; j < 4; ++j) {
                float wf = (float)(w0 + j);
                float ix = tc.ax * wf + bases_x;
                float iy = tc.ay * wf + bases_y;
                float ix0f = floorf(ix), iy0f = floorf(iy);
                float fx = ix - ix0f,   fy = iy - iy0f;
                int x0 = (int)ix0f, y0 = (int)iy0f;
                int x1 = x0 + 1,    y1 = y0 + 1;
                bool vx0 = (unsigned)x0 < (unsigned)W_;
                bool vx1 = (unsigned)x1 < (unsigned)W_;
                bool vy0 = (unsigned)y0 < (unsigned)H_;
                bool vy1 = (unsigned)y1 < (unsigned)H_;
                const float* r0 = Fc + (size_t)(vy0 ? y0 : 0) * W_;
                const float* r1 = Fc + (size_t)(vy1 ? y1 : 0) * W_;
                float v00 = (vy0 && vx0) ? __ldg(r0 + x0) : 0.f;
                float v01 = (vy0 && vx1) ? __ldg(r0 + x1) : 0.f;
                float v10 = (vy1 && vx0) ? __ldg(r1 + x0) : 0.f;
                float v11 = (vy1 && vx1) ? __ldg(r1 + x1) : 0.f;
                float wx0 = 1.f - fx, wx1 = fx;
                float wy0 = 1.f - fy, wy1 = fy;
                op[j] = wy0 * (wx0 * v00 + wx1 * v01) + wy1 * (wx0 * v10 + wx1 * v11);
            }
            __stcs(reinterpret_cast<float4*>(outp + (size_t)t * CHW_), o);
        }
    }
}

// ---------------------------------------------------------------------------
extern "C" void kernel_launch(void* const* d_in, const int* in_sizes, int n_in,
                              void* d_out, int out_size) {
    const float* F  = (const float*)d_in[0];
    const float* w1 = (const float*)d_in[1];
    const float* b1 = (const float*)d_in[2];
    const float* a  = (const float*)d_in[3];
    float* out = (float*)d_out;

    float* out_tail = out + (size_t)T_ * CHW_;

    gap_kernel<<<C_ * 4, 256>>>(F);
    theta_kernel<<<1, 256>>>(w1, b1, a, out_tail);

    dim3 blk(48, 8);              // 384 threads: w4 x 8 rows
    dim3 grd(H_ / 8, C_);         // 24 x 512 blocks
    sample_kernel<<<grd, blk>>>(F, out);
}

// round 17
// speedup vs baseline: 1.3567x; 1.0168x over previous
#include <cuda_runtime.h>
#include <math.h>

#define T_  4
#define C_  512
#define H_  192
#define W_  192
#define HW_ (H_ * W_)
#define CHW_ ((size_t)C_ * HW_)
#define W4_ (W_ / 4)

struct TCoef { float ax, bx, cx, ay, by, cy; };
struct TInt  { int k4, ky, s; float fx, fy; };

__device__ float  g_part[C_ * 8];
__device__ TCoef  g_tc[T_];
__device__ TInt   g_ti[T_];
__device__ int    g_fast;
__device__ float4 g_zero4;     // statically zero; never written — OOB load target

// ---------------------------------------------------------------------------
// Kernel 1: GAP, 8 partial blocks per channel (more CTA-level MLP vs 4-split)
// ---------------------------------------------------------------------------
__global__ void gap_kernel(const float* __restrict__ F) {
    int c = blockIdx.x >> 3;
    int q = blockIdx.x & 7;
    const int n4q = HW_ / 32;   // 1152 float4 per eighth
    const float4* p = reinterpret_cast<const float4*>(F + (size_t)c * HW_) + q * n4q;
    float s = 0.f;
    #pragma unroll
    for (int i = 0; i < 4; ++i) {            // 4 * 256 = 1024
        float4 v = p[i * 256 + threadIdx.x];
        s += (v.x + v.y) + (v.z + v.w);
    }
    if (threadIdx.x < 128) {                 // tail 128 (1152 - 1024)
        float4 v = p[1024 + threadIdx.x];
        s += (v.x + v.y) + (v.z + v.w);
    }
    #pragma unroll
    for (int o = 16; o > 0; o >>= 1) s += __shfl_xor_sync(0xffffffffu, s, o);
    __shared__ float sh[8];
    if ((threadIdx.x & 31) == 0) sh[threadIdx.x >> 5] = s;
    __syncthreads();
    if (threadIdx.x == 0) {
        float t = 0.f;
        #pragma unroll
        for (int i = 0; i < 8; ++i) t += sh[i];
        g_part[c * 8 + q] = t;
    }
}

// ---------------------------------------------------------------------------
// Kernel 2: theta (sums 8 partials per channel)
// ---------------------------------------------------------------------------
__global__ void theta_kernel(const float* __restrict__ w1,
                             const float* __restrict__ b1,
                             const float* __restrict__ a,
                             float* __restrict__ out_tail) {
    int warp = threadIdx.x >> 5;
    int lane = threadIdx.x & 31;

    float s = 0.f;
    for (int k = lane; k < C_; k += 32) {
        float4 p0 = *reinterpret_cast<const float4*>(&g_part[8 * k]);
        float4 p1 = *reinterpret_cast<const float4*>(&g_part[8 * k + 4]);
        float gsum = ((p0.x + p0.y) + (p0.z + p0.w))
                   + ((p1.x + p1.y) + (p1.z + p1.w));
        s += gsum * w1[warp * C_ + k];
    }
    #pragma unroll
    for (int o = 16; o > 0; o >>= 1) s += __shfl_xor_sync(0xffffffffu, s, o);

    __shared__ float Bs[2 * T_];
    if (lane == 0) Bs[warp] = tanhf(s * (1.0f / (float)HW_) + b1[warp]);
    __syncthreads();

    float a00 = a[0], a01 = a[1], a10 = a[2], a11 = a[3];

    if (threadIdx.x == 0)
        g_fast = (a00 == 1.0f && a01 == 0.0f && a10 == 0.0f && a11 == 1.0f) ? 1 : 0;

    if (threadIdx.x < T_) {
        int t = threadIdx.x;
        float bx = Bs[2 * t + 0];
        float by = Bs[2 * t + 1];
        TCoef tc;
        tc.ax = a00;
        tc.bx = a01 * ((float)W_ / (float)H_);
        tc.cx = 0.5f * (a00 - a00 * (float)W_ + a01 * ((float)W_ / (float)H_)
                        - a01 * (float)W_ + bx * (float)W_ + (float)W_ - 1.0f);
        tc.ay = a10 * ((float)H_ / (float)W_);
        tc.by = a11;
        tc.cy = 0.5f * (a10 * ((float)H_ / (float)W_) - a10 * (float)H_ + a11
                        - a11 * (float)H_ + by * (float)H_ + (float)H_ - 1.0f);
        g_tc[t] = tc;

        TInt ti;
        float kxf = floorf(tc.cx), kyf = floorf(tc.cy);
        int kx = (int)kxf;
        ti.ky = (int)kyf;
        ti.fx = tc.cx - kxf;
        ti.fy = tc.cy - kyf;
        ti.s  = kx & 3;
        ti.k4 = kx >> 2;          // floor(kx/4), exact for negatives
        g_ti[t] = ti;
    }

    if (threadIdx.x < T_ * 4) out_tail[threadIdx.x] = a[threadIdx.x & 3];
    if (threadIdx.x < 2 * T_) out_tail[T_ * 4 + threadIdx.x] = Bs[threadIdx.x];
}

// ---------------------------------------------------------------------------
// Kernel 3: bilinear warp — EXACT R14 body (proven 98.75us). Zero-redirect
// pointer trick for OOB; flat predication, no branches, no hoists.
// ---------------------------------------------------------------------------
__global__ void __launch_bounds__(384) sample_kernel(const float* __restrict__ F,
                                                     float* __restrict__ out) {
    int w4 = threadIdx.x;                    // 0..47
    int h  = blockIdx.x * 8 + threadIdx.y;   // 0..191
    int c  = blockIdx.y;                     // 0..511
    int w0 = w4 * 4;

    const float* Fc = F + (size_t)c * HW_;
    float* outp = out + (size_t)c * HW_ + (size_t)h * W_ + w0;
    const float4* zp = &g_zero4;

    if (g_fast) {
        #pragma unroll
        for (int t = 0; t < T_; ++t) {
            TInt ti = g_ti[t];
            int y0 = h + ti.ky;
            int base4 = w4 + ti.k4;
            bool vy0 = (unsigned)y0       < (unsigned)H_;
            bool vy1 = (unsigned)(y0 + 1) < (unsigned)H_;
            bool k0  = (unsigned)base4       < (unsigned)W4_;
            bool k1  = (unsigned)(base4 + 1) < (unsigned)W4_;

            const float4* r0 = reinterpret_cast<const float4*>(Fc) + y0 * W4_;
            const float4* r1 = r0 + W4_;

            const float4* q00 = (vy0 && k0) ? r0 + base4     : zp;
            const float4* q01 = (vy0 && k1) ? r0 + base4 + 1 : zp;
            const float4* q10 = (vy1 && k0) ? r1 + base4     : zp;
            const float4* q11 = (vy1 && k1) ? r1 + base4 + 1 : zp;

            float4 A0 = __ldg(q00);
            float4 A1 = __ldg(q01);
            float4 B0 = __ldg(q10);
            float4 B1 = __ldg(q11);

            float fy = ti.fy;
            float m0 = A0.x + fy * (B0.x - A0.x);
            float m1 = A0.y + fy * (B0.y - A0.y);
            float m2 = A0.z + fy * (B0.z - A0.z);
            float m3 = A0.w + fy * (B0.w - A0.w);
            float m4 = A1.x + fy * (B1.x - A1.x);
            float m5 = A1.y + fy * (B1.y - A1.y);
            float m6 = A1.z + fy * (B1.z - A1.z);
            float m7 = A1.w + fy * (B1.w - A1.w);

            float fx = ti.fx;
            float4 o;
            #define MIX_(e0, e1) ((e0) + fx * ((e1) - (e0)))
            switch (ti.s) {   // uniform branch: all warps take the same case
                case 0: o.x=MIX_(m0,m1); o.y=MIX_(m1,m2); o.z=MIX_(m2,m3); o.w=MIX_(m3,m4); break;
                case 1: o.x=MIX_(m1,m2); o.y=MIX_(m2,m3); o.z=MIX_(m3,m4); o.w=MIX_(m4,m5); break;
                case 2: o.x=MIX_(m2,m3); o.y=MIX_(m3,m4); o.z=MIX_(m4,m5); o.w=MIX_(m5,m6); break;
                default:o.x=MIX_(m3,m4); o.y=MIX_(m4,m5); o.z=MIX_(m5,m6); o.w=MIX_(m6,m7); break;
            }
            #undef MIX_
            __stcs(reinterpret_cast<float4*>(outp + (size_t)t * CHW_), o);
        }
    } else {
        // General affine fallback (scalar gathers)
        #pragma unroll
        for (int t = 0; t < T_; ++t) {
            TCoef tc = g_tc[t];
            float bases_x = tc.bx * (float)h + tc.cx;
            float bases_y = tc.by * (float)h + tc.cy;
            float4 o;
            float* op = reinterpret_cast<float*>(&o);
            #pragma unroll
            for (int j = 0; j < 4; ++j) {
                float wf = (float)(w0 + j);
                float ix = tc.ax * wf + bases_x;
                float iy = tc.ay * wf + bases_y;
                float ix0f = floorf(ix), iy0f = floorf(iy);
                float fx = ix - ix0f,   fy = iy - iy0f;
                int x0 = (int)ix0f, y0 = (int)iy0f;
                int x1 = x0 + 1,    y1 = y0 + 1;
                bool vx0 = (unsigned)x0 < (unsigned)W_;
                bool vx1 = (unsigned)x1 < (unsigned)W_;
                bool vy0 = (unsigned)y0 < (unsigned)H_;
                bool vy1 = (unsigned)y1 < (unsigned)H_;
                const float* r0 = Fc + (size_t)(vy0 ? y0 : 0) * W_;
                const float* r1 = Fc + (size_t)(vy1 ? y1 : 0) * W_;
                float v00 = (vy0 && vx0) ? __ldg(r0 + x0) : 0.f;
                float v01 = (vy0 && vx1) ? __ldg(r0 + x1) : 0.f;
                float v10 = (vy1 && vx0) ? __ldg(r1 + x0) : 0.f;
                float v11 = (vy1 && vx1) ? __ldg(r1 + x1) : 0.f;
                float wx0 = 1.f - fx, wx1 = fx;
                float wy0 = 1.f - fy, wy1 = fy;
                op[j] = wy0 * (wx0 * v00 + wx1 * v01) + wy1 * (wx0 * v10 + wx1 * v11);
            }
            __stcs(reinterpret_cast<float4*>(outp + (size_t)t * CHW_), o);
        }
    }
}

// ---------------------------------------------------------------------------
extern "C" void kernel_launch(void* const* d_in, const int* in_sizes, int n_in,
                              void* d_out, int out_size) {
    const float* F  = (const float*)d_in[0];
    const float* w1 = (const float*)d_in[1];
    const float* b1 = (const float*)d_in[2];
    const float* a  = (const float*)d_in[3];
    float* out = (float*)d_out;

    float* out_tail = out + (size_t)T_ * CHW_;

    gap_kernel<<<C_ * 8, 256>>>(F);
    theta_kernel<<<1, 256>>>(w1, b1, a, out_tail);

    dim3 blk(48, 8);              // 384 threads: w4 x 8 rows
    dim3 grd(H_ / 8, C_);         // 24 x 512 blocks
    sample_kernel<<<grd, blk>>>(F, out);
}